// round 7
// baseline (speedup 1.0000x reference)
#include <cuda_runtime.h>
#include <math.h>

// ---------------------------------------------------------------------------
// Problem constants
// ---------------------------------------------------------------------------
constexpr int H_    = 93;
constexpr int W_    = 44;
constexpr int HW_   = H_ * W_;      // 4092
constexpr int B_    = 8;
constexpr int HID_  = 128;
constexpr int LAT_  = 1024;
constexpr int MAXN_ = 24;
constexpr int OFF1  = B_ * HW_ * 2; // 65472  (mask_indices start, as float)
constexpr int OFF2  = 2 * OFF1;     // 130944 (valid_mask start, as float)
constexpr int NT4   = 8256;         // border warp-tasks (1032 positions x 8 b)

// ---------------------------------------------------------------------------
// Scratch (__device__ globals: no allocation allowed)
// ---------------------------------------------------------------------------
__device__ __align__(16) float g_lcpart[B_ * 8 * HID_]; // latent GEMV partials
__device__ __align__(16) float g_lc  [B_ * HID_];
__device__ __align__(16) float g_T   [B_ * 9 * HID_];   // taps
__device__ __align__(16) float g_F25 [B_ * 25 * HID_];
__device__ __align__(16) float g_s25 [B_ * 25];
__device__ __align__(16) float g_Y   [B_ * 25 * HID_];
__device__ __align__(16) float g_base[B_ * HID_];
__device__ int g_slot[B_ * HW_];                        // packed slot or -1
__device__ unsigned g_bar;                              // monotonic barrier

__device__ __forceinline__ float gelu_(float x) {
    return 0.5f * x * (1.0f + erff(x * 0.70710678118654752440f));
}

__device__ __forceinline__ void warp_red4(float4& a) {
    for (int off = 16; off >= 1; off >>= 1) {
        a.x += __shfl_xor_sync(0xffffffffu, a.x, off);
        a.y += __shfl_xor_sync(0xffffffffu, a.y, off);
        a.z += __shfl_xor_sync(0xffffffffu, a.z, off);
        a.w += __shfl_xor_sync(0xffffffffu, a.w, off);
    }
}

// rowmap[out_row_class][tap] -> input row-class (0=top,1=mid,2=bot), -1 = OOB
__constant__ int c_map[5][3] = {
    {-1, 0, 1}, { 0, 1, 1}, { 1, 1, 1}, { 1, 1, 2}, { 1, 2,-1},
};

// ---------------------------------------------------------------------------
// Software grid barrier. grid == #SMs, occupancy 1 => all blocks resident.
// Monotonic counter, correct across arbitrarily many graph replays.
// ---------------------------------------------------------------------------
__device__ __forceinline__ void grid_bar() {
    __syncthreads();
    if (threadIdx.x == 0) {
        __threadfence();
        unsigned old = atomicAdd(&g_bar, 1u);
        unsigned target = old - (old % gridDim.x) + gridDim.x;
        while (*(volatile unsigned*)&g_bar < target) { __nanosleep(32); }
        __threadfence();
    }
    __syncthreads();
}

// ---------------------------------------------------------------------------
// Shared memory union (max member = 36 KB < 48 KB static limit)
// ---------------------------------------------------------------------------
union __align__(16) SmemU {
    struct { int wsum[32]; } p1;
    struct { float redc[8 * HID_]; float s_lc[HID_]; } p2;
    struct { float g9s[B_ * 9 * HID_]; } p3;            // 36 KB
    struct { float wc[32][25]; float sPint[8][2]; } p5;
};

// ---------------------------------------------------------------------------
// The one persistent kernel
// ---------------------------------------------------------------------------
__global__ __launch_bounds__(1024, 1) void kFused(
    const float* __restrict__ lat,  const int* __restrict__ mask,
    const int* __restrict__ nidx,   const int* __restrict__ ncnt,
    const float* __restrict__ Wl,   const float* __restrict__ bl,
    const float* __restrict__ Wt,   const float* __restrict__ bt,
    const float* __restrict__ g1,   const float* __restrict__ b1g,
    const float* __restrict__ Wc,   const float* __restrict__ bc,
    const float* __restrict__ Wa,   const float* __restrict__ ba,
    const float* __restrict__ W1,   const float* __restrict__ b1,
    const float* __restrict__ W2,   const float* __restrict__ b2,
    float* __restrict__ out) {

    __shared__ SmemU su;
    const int tid  = threadIdx.x;
    const int blk  = blockIdx.x;
    const int grid = gridDim.x;

    // =====================================================================
    // Phase 1: tasks 0..63 -> latent GEMV partials (b x i-chunk)
    //          tasks 64..71 -> per-batch scan + output init + g_slot
    // =====================================================================
    for (int t = blk; t < 72; t += grid) {
        if (t < 64) {
            int b = t >> 3, ch = t & 7;
            int s = tid & 31, o4 = tid >> 5;
            float4 la = *(const float4*)&lat[b * LAT_ + ch * 128 + s * 4];
            const float* wb = Wl + (size_t)(ch * 128 + s * 4) * HID_ + o4 * 4;
            float4 acc = make_float4(0.f, 0.f, 0.f, 0.f);
            #pragma unroll
            for (int k = 0; k < 4; k++) {
                float lk = (&la.x)[k];
                float4 w = *(const float4*)(wb + k * HID_);
                acc.x = fmaf(lk, w.x, acc.x);
                acc.y = fmaf(lk, w.y, acc.y);
                acc.z = fmaf(lk, w.z, acc.z);
                acc.w = fmaf(lk, w.w, acc.w);
            }
            warp_red4(acc);
            if (s == 0)
                *(float4*)&g_lcpart[(b * 8 + ch) * HID_ + o4 * 4] = acc;
        } else {
            int b = t - 64;
            int lane = tid & 31, warp = tid >> 5;
            int base = tid * 4;
            int m[4], loc[4];
            int s = 0;
            for (int j = 0; j < 4; j++) {
                int p = base + j;
                int mm = (p < HW_) ? (mask[b * HW_ + p] > 0) : 0;
                m[j] = mm; loc[j] = s; s += mm;
            }
            int v = s;
            for (int off = 1; off < 32; off <<= 1) {
                int u = __shfl_up_sync(0xffffffffu, v, off);
                if (lane >= off) v += u;
            }
            if (lane == 31) su.p1.wsum[warp] = v;
            __syncthreads();
            if (warp == 0) {
                int wv = su.p1.wsum[lane];
                for (int off = 1; off < 32; off <<= 1) {
                    int u = __shfl_up_sync(0xffffffffu, wv, off);
                    if (lane >= off) wv += u;
                }
                su.p1.wsum[lane] = wv;
            }
            __syncthreads();
            int excl = (v - s) + (warp > 0 ? su.p1.wsum[warp - 1] : 0);
            int nm = su.p1.wsum[31];   // total masked this row

            for (int j = 0; j < 4; j++) {
                int p = base + j;
                if (p < HW_) {
                    if (m[j]) {
                        int slot = excl + loc[j];
                        out[OFF1 + (b * HW_ + slot) * 2]     = (float)(p / W_);
                        out[OFF1 + (b * HW_ + slot) * 2 + 1] = (float)(p % W_);
                        g_slot[b * HW_ + p] = slot;
                    } else {
                        g_slot[b * HW_ + p] = -1;
                    }
                }
            }
            // zero unused tail slots + write valid row
            for (int sl = nm + tid; sl < HW_; sl += 1024) {
                out[(b * HW_ + sl) * 2]            = 0.f;
                out[(b * HW_ + sl) * 2 + 1]        = 0.f;
                out[OFF1 + (b * HW_ + sl) * 2]     = 0.f;
                out[OFF1 + (b * HW_ + sl) * 2 + 1] = 0.f;
            }
            for (int sl = tid; sl < HW_; sl += 1024)
                out[OFF2 + b * HW_ + sl] = (sl < nm) ? 1.f : 0.f;
        }
    }
    grid_bar();

    // =====================================================================
    // Phase 2: 72 tasks (b, tap): reduce lc partials (+gelu), then taps
    // =====================================================================
    for (int t = blk; t < 72; t += grid) {
        int b = t / 9, tp = t % 9;
        {
            int o = tid & 127, ch = tid >> 7;
            su.p2.redc[ch * 128 + o] = g_lcpart[(b * 8 + ch) * HID_ + o];
            __syncthreads();
            for (int st = 4; st >= 1; st >>= 1) {
                if (ch < st) su.p2.redc[ch * 128 + o] += su.p2.redc[(ch + st) * 128 + o];
                __syncthreads();
            }
            if (tid < HID_) {
                float v = gelu_(su.p2.redc[tid] + bl[tid]);
                su.p2.s_lc[tid] = v;
                if (tp == 0) g_lc[b * HID_ + tid] = v;
            }
            __syncthreads();
        }
        int s = tid & 31, o4 = tid >> 5;
        float4 lc4 = *(const float4*)&su.p2.s_lc[s * 4];
        const float* wb = Wt + (size_t)tp * HID_ * HID_ + (size_t)(s * 4) * HID_ + o4 * 4;
        float4 acc = make_float4(0.f, 0.f, 0.f, 0.f);
        #pragma unroll
        for (int k = 0; k < 4; k++) {
            float lk = (&lc4.x)[k];
            float4 w = *(const float4*)(wb + k * HID_);
            acc.x = fmaf(lk, w.x, acc.x);
            acc.y = fmaf(lk, w.y, acc.y);
            acc.z = fmaf(lk, w.z, acc.z);
            acc.w = fmaf(lk, w.w, acc.w);
        }
        warp_red4(acc);
        if (s == 0)
            *(float4*)&g_T[(b * 9 + tp) * HID_ + o4 * 4] = acc;
        __syncthreads();   // protect smem before next task iteration
    }
    grid_bar();

    // =====================================================================
    // Phase 3: every block recomputes GN->g9s in smem, then conv2 tasks
    //          200 tasks (cls x og16) grid-strided
    // =====================================================================
    {
        int b = tid >> 7, o = tid & 127;
        float Tl[9];
        #pragma unroll
        for (int t9 = 0; t9 < 9; t9++) Tl[t9] = g_T[(b * 9 + t9) * HID_ + o];
        float btv = bt[o];

        float c9[9];
        for (int rc = 0; rc < 3; rc++)
            for (int cc = 0; cc < 3; cc++) {
                float sum = btv;
                for (int kh = 0; kh < 3; kh++) {
                    if ((rc == 0 && kh == 0) || (rc == 2 && kh == 2)) continue;
                    for (int kw = 0; kw < 3; kw++) {
                        if ((cc == 0 && kw == 0) || (cc == 2 && kw == 2)) continue;
                        sum += Tl[kh * 3 + kw];
                    }
                }
                c9[rc * 3 + cc] = sum;
            }

        const float rowcnt[3] = {1.f, (float)(H_ - 2), 1.f};
        const float colcnt[3] = {1.f, (float)(W_ - 2), 1.f};
        float area[9];
        for (int rc = 0; rc < 3; rc++)
            for (int cc = 0; cc < 3; cc++)
                area[rc * 3 + cc] = rowcnt[rc] * colcnt[cc];

        const float inv = 1.0f / (16.0f * (float)HW_);
        float sm = 0.f;
        for (int k = 0; k < 9; k++) sm += area[k] * c9[k];
        for (int off = 8; off >= 1; off >>= 1) sm += __shfl_xor_sync(0xffffffffu, sm, off);
        float mean = sm * inv;

        float d = 0.f;
        for (int k = 0; k < 9; k++) { float tt = c9[k] - mean; d += area[k] * tt * tt; }
        for (int off = 8; off >= 1; off >>= 1) d += __shfl_xor_sync(0xffffffffu, d, off);
        float rstd = rsqrtf(d * inv + 1e-5f);

        float ga = g1[o], be = b1g[o];
        for (int k = 0; k < 9; k++)
            su.p3.g9s[(b * 9 + k) * HID_ + o] = gelu_((c9[k] - mean) * rstd * ga + be);
        __syncthreads();
    }
    for (int t = blk; t < 200; t += grid) {
        int cls = t >> 3, og = t & 7;
        int orc = cls / 5, occ = cls % 5;
        int s = tid & 31, o4 = (tid >> 5) & 3, b = tid >> 7;
        int o = og * 16 + o4 * 4;

        float4 acc = make_float4(0.f, 0.f, 0.f, 0.f);
        for (int kh = 0; kh < 3; kh++) {
            int ir = c_map[orc][kh];
            if (ir < 0) continue;
            for (int kw = 0; kw < 3; kw++) {
                int ic = c_map[occ][kw];
                if (ic < 0) continue;
                float4 g4 = *(const float4*)&su.p3.g9s[(b * 9 + ir * 3 + ic) * HID_ + s * 4];
                const float* wb = Wc + ((size_t)(kh * 3 + kw) * HID_ + s * 4) * HID_ + o;
                #pragma unroll
                for (int k = 0; k < 4; k++) {
                    float gk = (&g4.x)[k];
                    float4 w = *(const float4*)(wb + k * HID_);
                    acc.x = fmaf(gk, w.x, acc.x);
                    acc.y = fmaf(gk, w.y, acc.y);
                    acc.z = fmaf(gk, w.z, acc.z);
                    acc.w = fmaf(gk, w.w, acc.w);
                }
            }
        }
        warp_red4(acc);
        if (s == 0) {
            float4 bcv = *(const float4*)&bc[o];
            acc.x = gelu_(acc.x + bcv.x);
            acc.y = gelu_(acc.y + bcv.y);
            acc.z = gelu_(acc.z + bcv.z);
            acc.w = gelu_(acc.w + bcv.w);
            *(float4*)&g_F25[(b * 25 + cls) * HID_ + o] = acc;
        }
    }
    grid_bar();

    // =====================================================================
    // Phase 4: 208 tasks (b x 26): cls<25 -> Y + s25 ; cls==25 -> base
    // =====================================================================
    for (int t = blk; t < 208; t += grid) {
        int b = t / 26, cls = t % 26;
        int s = tid & 31, o4 = tid >> 5;

        float4 x4;
        const float* wb;
        if (cls < 25) {
            x4 = *(const float4*)&g_F25[(b * 25 + cls) * HID_ + s * 4];
            wb = W1 + (size_t)(s * 4) * HID_ + o4 * 4;
        } else {
            x4 = *(const float4*)&g_lc[b * HID_ + s * 4];
            wb = W1 + (size_t)(HID_ + s * 4) * HID_ + o4 * 4;
        }
        float4 acc = make_float4(0.f, 0.f, 0.f, 0.f);
        #pragma unroll
        for (int k = 0; k < 4; k++) {
            float xk = (&x4.x)[k];
            float4 w = *(const float4*)(wb + k * HID_);
            acc.x = fmaf(xk, w.x, acc.x);
            acc.y = fmaf(xk, w.y, acc.y);
            acc.z = fmaf(xk, w.z, acc.z);
            acc.w = fmaf(xk, w.w, acc.w);
        }
        warp_red4(acc);
        if (cls < 25) {
            if (s == 0)
                *(float4*)&g_Y[(b * 25 + cls) * HID_ + o4 * 4] = acc;
            if (o4 == 0) {
                float sv = x4.x * Wa[s * 4]     + x4.y * Wa[s * 4 + 1]
                         + x4.z * Wa[s * 4 + 2] + x4.w * Wa[s * 4 + 3];
                for (int off = 16; off >= 1; off >>= 1)
                    sv += __shfl_xor_sync(0xffffffffu, sv, off);
                if (s == 0) g_s25[b * 25 + cls] = sv + ba[0];
            }
        } else if (s == 0) {
            float4 b14 = *(const float4*)&b1[o4 * 4];
            acc.x += b14.x; acc.y += b14.y; acc.z += b14.z; acc.w += b14.w;
            *(float4*)&g_base[b * HID_ + o4 * 4] = acc;
        }
    }
    grid_bar();

    // =====================================================================
    // Phase 5: Pint (redundant per block), interior fill, border attention.
    //          All writes go straight to packed output slots via g_slot.
    // =====================================================================
    {
        const int warp = tid >> 5, lane = tid & 31;
        if (warp < 8) {
            int b = warp;
            float4 y4  = *(const float4*)&g_Y[(b * 25 + 12) * HID_ + lane * 4];
            float4 bs4 = *(const float4*)&g_base[b * HID_ + lane * 4];
            float hx = gelu_(y4.x + bs4.x), hy = gelu_(y4.y + bs4.y);
            float hz = gelu_(y4.z + bs4.z), hw = gelu_(y4.w + bs4.w);
            float4 w2a = *(const float4*)&W2[lane * 8];
            float4 w2b = *(const float4*)&W2[lane * 8 + 4];
            float p0 = hx * w2a.x + hy * w2a.z + hz * w2b.x + hw * w2b.z;
            float p1 = hx * w2a.y + hy * w2a.w + hz * w2b.y + hw * w2b.w;
            for (int off = 16; off >= 1; off >>= 1) {
                p0 += __shfl_xor_sync(0xffffffffu, p0, off);
                p1 += __shfl_xor_sync(0xffffffffu, p1, off);
            }
            if (lane == 0) {
                su.p5.sPint[b][0] = p0 + b2[0];
                su.p5.sPint[b][1] = p1 + b2[1];
            }
        }
        __syncthreads();

        // interior masked slots -> Pint
        for (int idx = blk * 1024 + tid; idx < 8 * 4096; idx += grid * 1024) {
            int b = idx >> 12, pp = idx & 4095;
            if (pp < HW_) {
                int slot = g_slot[b * HW_ + pp];
                if (slot >= 0) {
                    int r = pp / W_, c = pp % W_;
                    if (r >= 4 && r <= H_ - 5 && c >= 4 && c <= W_ - 5) {
                        out[(b * HW_ + slot) * 2]     = su.p5.sPint[b][0];
                        out[(b * HW_ + slot) * 2 + 1] = su.p5.sPint[b][1];
                    }
                }
            }
        }

        // border attention (masked positions only)
        float* wcw = su.p5.wc[warp];
        const float b20 = b2[0], b21 = b2[1];
        const int nwarp = grid * 32;
        for (int task = blk * 32 + warp; task < NT4; task += nwarp) {
            int j = task >> 3, b = task & 7;
            int r, c;
            if (j < 176)      { r = j / 44;                 c = j % 44; }
            else if (j < 352) { int j2 = j - 176; r = 89 + j2 / 44; c = j2 % 44; }
            else              { int j3 = j - 352; r = 4 + j3 / 8;
                                int k = j3 % 8; c = (k < 4) ? k : 36 + k; }
            int p = r * W_ + c;
            int slot = g_slot[b * HW_ + p];
            if (slot < 0) continue;   // unmasked: not in output

            if (lane < 25) wcw[lane] = 0.f;
            __syncwarp();

            bool has = lane < MAXN_;
            float logit = -3.0e38f;
            int cls = 0;
            if (has) {
                int idx = nidx[p * MAXN_ + lane];
                int rr = idx / W_, c2 = idx % W_;
                int rc = (rr == 0) ? 0 : (rr == 1) ? 1 : (rr == H_ - 2) ? 3 : (rr == H_ - 1) ? 4 : 2;
                int cc = (c2 == 0) ? 0 : (c2 == 1) ? 1 : (c2 == W_ - 2) ? 3 : (c2 == W_ - 1) ? 4 : 2;
                cls = rc * 5 + cc;
                bool valid = (lane < ncnt[p]) && (mask[b * HW_ + idx] == 0);
                logit = valid ? g_s25[b * 25 + cls] : -10000.0f;
            }
            float m = logit;
            for (int off = 16; off >= 1; off >>= 1)
                m = fmaxf(m, __shfl_xor_sync(0xffffffffu, m, off));
            float e = has ? expf(logit - m) : 0.f;
            float se = e;
            for (int off = 16; off >= 1; off >>= 1)
                se += __shfl_xor_sync(0xffffffffu, se, off);
            float wgt = e / se;
            if (has && wgt != 0.f) atomicAdd(&wcw[cls], wgt);
            __syncwarp();

            float4 acc = *(const float4*)&g_base[b * HID_ + lane * 4];
            #pragma unroll
            for (int cl = 0; cl < 25; cl++) {
                float wv = wcw[cl];
                if (wv != 0.f) {
                    float4 y = *(const float4*)&g_Y[(b * 25 + cl) * HID_ + lane * 4];
                    acc.x = fmaf(wv, y.x, acc.x);
                    acc.y = fmaf(wv, y.y, acc.y);
                    acc.z = fmaf(wv, y.z, acc.z);
                    acc.w = fmaf(wv, y.w, acc.w);
                }
            }
            float hx = gelu_(acc.x), hy = gelu_(acc.y), hz = gelu_(acc.z), hw = gelu_(acc.w);
            float4 w2a = *(const float4*)&W2[lane * 8];
            float4 w2b = *(const float4*)&W2[lane * 8 + 4];
            float p0 = hx * w2a.x + hy * w2a.z + hz * w2b.x + hw * w2b.z;
            float p1 = hx * w2a.y + hy * w2a.w + hz * w2b.y + hw * w2b.w;
            for (int off = 16; off >= 1; off >>= 1) {
                p0 += __shfl_xor_sync(0xffffffffu, p0, off);
                p1 += __shfl_xor_sync(0xffffffffu, p1, off);
            }
            if (lane == 0) {
                out[(b * HW_ + slot) * 2]     = p0 + b20;
                out[(b * HW_ + slot) * 2 + 1] = p1 + b21;
            }
            __syncwarp();
        }
    }
}

// ---------------------------------------------------------------------------
// kernel_launch — single persistent node
// ---------------------------------------------------------------------------
extern "C" void kernel_launch(void* const* d_in, const int* in_sizes, int n_in,
                              void* d_out, int out_size) {
    const float* latent = (const float*)d_in[1];
    const int*   mask   = (const int*)  d_in[2];
    const int*   nidx   = (const int*)  d_in[3];
    const int*   ncnt   = (const int*)  d_in[4];
    const float* Wl = (const float*)d_in[5];
    const float* bl = (const float*)d_in[6];
    const float* Wt = (const float*)d_in[7];
    const float* bt = (const float*)d_in[8];
    const float* g1 = (const float*)d_in[9];
    const float* b1g= (const float*)d_in[10];
    const float* Wc = (const float*)d_in[11];
    const float* bc = (const float*)d_in[12];
    const float* Wa = (const float*)d_in[13];
    const float* ba = (const float*)d_in[14];
    const float* W1 = (const float*)d_in[15];
    const float* b1 = (const float*)d_in[16];
    const float* W2 = (const float*)d_in[17];
    const float* b2 = (const float*)d_in[18];

    int nsm = 148;
    cudaDeviceGetAttribute(&nsm, cudaDevAttrMultiProcessorCount, 0);

    kFused<<<nsm, 1024>>>(latent, mask, nidx, ncnt,
                          Wl, bl, Wt, bt, g1, b1g, Wc, bc,
                          Wa, ba, W1, b1, W2, b2,
                          (float*)d_out);
}

// round 8
// speedup vs baseline: 1.7371x; 1.7371x over previous
#include <cuda_runtime.h>
#include <math.h>

// ---------------------------------------------------------------------------
// Problem constants
// ---------------------------------------------------------------------------
constexpr int H_    = 93;
constexpr int W_    = 44;
constexpr int HW_   = H_ * W_;      // 4092
constexpr int B_    = 8;
constexpr int HID_  = 128;
constexpr int LAT_  = 1024;
constexpr int MAXN_ = 24;
constexpr int OFF1  = B_ * HW_ * 2; // 65472  (mask_indices start, as float)
constexpr int OFF2  = 2 * OFF1;     // 130944 (valid_mask start, as float)
constexpr int NT4   = 8256;         // border warp-tasks (1032 positions x 8 b)

// ---------------------------------------------------------------------------
// Scratch (__device__ globals: no allocation allowed)
// ---------------------------------------------------------------------------
__device__ __align__(16) float g_lcpart[B_ * 8 * HID_]; // latent GEMV partials
__device__ __align__(16) float g_lc  [B_ * HID_];
__device__ __align__(16) float g_T   [B_ * 9 * HID_];   // taps
__device__ __align__(16) float g_F25 [B_ * 25 * HID_];
__device__ __align__(16) float g_s25 [B_ * 25];
__device__ __align__(16) float g_Y   [B_ * 25 * HID_];
__device__ __align__(16) float g_base[B_ * HID_];
__device__ int g_slot[B_ * HW_];                        // packed slot or -1
__device__ unsigned g_bar;                              // monotonic barrier

__device__ __forceinline__ float gelu_(float x) {
    return 0.5f * x * (1.0f + erff(x * 0.70710678118654752440f));
}

// rowmap[out_row_class][tap] -> input row-class (0=top,1=mid,2=bot), -1 = OOB
__constant__ int c_map[5][3] = {
    {-1, 0, 1}, { 0, 1, 1}, { 1, 1, 1}, { 1, 1, 2}, { 1, 2,-1},
};

// ---------------------------------------------------------------------------
// Software grid barrier (monotonic counter; grid == #SMs, occupancy 1)
// ---------------------------------------------------------------------------
__device__ __forceinline__ void grid_bar() {
    __syncthreads();
    if (threadIdx.x == 0) {
        __threadfence();
        unsigned old = atomicAdd(&g_bar, 1u);
        unsigned target = old - (old % gridDim.x) + gridDim.x;
        while (*(volatile unsigned*)&g_bar < target) { __nanosleep(32); }
        __threadfence();
    }
    __syncthreads();
}

// ---------------------------------------------------------------------------
// Block-wide reduction of per-warp float4 partials (32 warps -> warp 0).
// Layout: lanes own 4 contiguous outputs; warp s holds partial for i-chunk s.
// ---------------------------------------------------------------------------
__device__ __forceinline__ void block_red4(float4* red4, int s, int lane, float4& acc) {
    red4[s * 32 + lane] = acc;
    __syncthreads();
    #pragma unroll
    for (int st = 16; st >= 1; st >>= 1) {
        if (s < st) {
            float4 o = red4[(s + st) * 32 + lane];
            float4 m = red4[s * 32 + lane];
            m.x += o.x; m.y += o.y; m.z += o.z; m.w += o.w;
            red4[s * 32 + lane] = m;
        }
        __syncthreads();
    }
    if (s == 0) acc = red4[lane];
}

// ---------------------------------------------------------------------------
// Shared memory union (max member ~21 KB < 48 KB static limit)
// ---------------------------------------------------------------------------
union __align__(16) SmemU {
    struct { float4 red4[1024]; int wsum[32]; } p1;
    struct { float redc[8 * HID_]; float s_lc[HID_]; float4 red4[1024]; } p2;
    struct { float g9b[9 * HID_]; float4 red4[1024]; } p3;
    struct { float4 red4[1024]; float sred[32]; } p4;
    struct { float wc[32][25]; float sPint[8][2]; } p5;
};

// ---------------------------------------------------------------------------
// The one persistent kernel
// ---------------------------------------------------------------------------
__global__ __launch_bounds__(1024, 1) void kFused(
    const float* __restrict__ lat,  const int* __restrict__ mask,
    const int* __restrict__ nidx,   const int* __restrict__ ncnt,
    const float* __restrict__ Wl,   const float* __restrict__ bl,
    const float* __restrict__ Wt,   const float* __restrict__ bt,
    const float* __restrict__ g1,   const float* __restrict__ b1g,
    const float* __restrict__ Wc,   const float* __restrict__ bc,
    const float* __restrict__ Wa,   const float* __restrict__ ba,
    const float* __restrict__ W1,   const float* __restrict__ b1,
    const float* __restrict__ W2,   const float* __restrict__ b2,
    float* __restrict__ out) {

    __shared__ SmemU su;
    const int tid  = threadIdx.x;
    const int blk  = blockIdx.x;
    const int grid = gridDim.x;
    const int lane = tid & 31;
    const int s    = tid >> 5;      // warp id = i-chunk for GEMV phases

    // =====================================================================
    // Phase 1: tasks 0..63  -> latent GEMV partials (b x i-chunk128)
    //          tasks 64..71 -> per-batch scan + output init + g_slot
    // =====================================================================
    for (int t = blk; t < 72; t += grid) {
        if (t < 64) {
            int b = t >> 3, ch = t & 7;
            float4 x4 = *(const float4*)&lat[b * LAT_ + ch * 128 + s * 4];
            const float* wb = Wl + (size_t)(ch * 128 + s * 4) * HID_ + lane * 4;
            float4 acc = make_float4(0.f, 0.f, 0.f, 0.f);
            #pragma unroll
            for (int k = 0; k < 4; k++) {
                float xk = (&x4.x)[k];
                float4 w = *(const float4*)(wb + (size_t)k * HID_);
                acc.x = fmaf(xk, w.x, acc.x);
                acc.y = fmaf(xk, w.y, acc.y);
                acc.z = fmaf(xk, w.z, acc.z);
                acc.w = fmaf(xk, w.w, acc.w);
            }
            block_red4(su.p1.red4, s, lane, acc);
            if (s == 0)
                *(float4*)&g_lcpart[(b * 8 + ch) * HID_ + lane * 4] = acc;
        } else {
            int b = t - 64;
            int warp = s;
            int base = tid * 4;
            int m[4], loc[4];
            int sc = 0;
            for (int j = 0; j < 4; j++) {
                int p = base + j;
                int mm = (p < HW_) ? (mask[b * HW_ + p] > 0) : 0;
                m[j] = mm; loc[j] = sc; sc += mm;
            }
            int v = sc;
            for (int off = 1; off < 32; off <<= 1) {
                int u = __shfl_up_sync(0xffffffffu, v, off);
                if (lane >= off) v += u;
            }
            if (lane == 31) su.p1.wsum[warp] = v;
            __syncthreads();
            if (warp == 0) {
                int wv = su.p1.wsum[lane];
                for (int off = 1; off < 32; off <<= 1) {
                    int u = __shfl_up_sync(0xffffffffu, wv, off);
                    if (lane >= off) wv += u;
                }
                su.p1.wsum[lane] = wv;
            }
            __syncthreads();
            int excl = (v - sc) + (warp > 0 ? su.p1.wsum[warp - 1] : 0);
            int nm = su.p1.wsum[31];

            for (int j = 0; j < 4; j++) {
                int p = base + j;
                if (p < HW_) {
                    if (m[j]) {
                        int slot = excl + loc[j];
                        out[OFF1 + (b * HW_ + slot) * 2]     = (float)(p / W_);
                        out[OFF1 + (b * HW_ + slot) * 2 + 1] = (float)(p % W_);
                        g_slot[b * HW_ + p] = slot;
                    } else {
                        g_slot[b * HW_ + p] = -1;
                    }
                }
            }
            for (int sl = nm + tid; sl < HW_; sl += 1024) {
                out[(b * HW_ + sl) * 2]            = 0.f;
                out[(b * HW_ + sl) * 2 + 1]        = 0.f;
                out[OFF1 + (b * HW_ + sl) * 2]     = 0.f;
                out[OFF1 + (b * HW_ + sl) * 2 + 1] = 0.f;
            }
            for (int sl = tid; sl < HW_; sl += 1024)
                out[OFF2 + b * HW_ + sl] = (sl < nm) ? 1.f : 0.f;
        }
    }
    grid_bar();

    // =====================================================================
    // Phase 2: 72 tasks (b, tap): reduce lc partials (+gelu), then tap GEMV
    // =====================================================================
    for (int t = blk; t < 72; t += grid) {
        int b = t / 9, tp = t % 9;
        {
            int o = tid & 127, ch = tid >> 7;
            su.p2.redc[ch * 128 + o] = g_lcpart[(b * 8 + ch) * HID_ + o];
            __syncthreads();
            for (int st = 4; st >= 1; st >>= 1) {
                if (ch < st) su.p2.redc[ch * 128 + o] += su.p2.redc[(ch + st) * 128 + o];
                __syncthreads();
            }
            if (tid < HID_) {
                float v = gelu_(su.p2.redc[tid] + bl[tid]);
                su.p2.s_lc[tid] = v;
                if (tp == 0) g_lc[b * HID_ + tid] = v;
            }
            __syncthreads();
        }
        float4 x4 = *(const float4*)&su.p2.s_lc[s * 4];
        const float* wb = Wt + (size_t)tp * HID_ * HID_ + (size_t)(s * 4) * HID_ + lane * 4;
        float4 acc = make_float4(0.f, 0.f, 0.f, 0.f);
        #pragma unroll
        for (int k = 0; k < 4; k++) {
            float xk = (&x4.x)[k];
            float4 w = *(const float4*)(wb + (size_t)k * HID_);
            acc.x = fmaf(xk, w.x, acc.x);
            acc.y = fmaf(xk, w.y, acc.y);
            acc.z = fmaf(xk, w.z, acc.z);
            acc.w = fmaf(xk, w.w, acc.w);
        }
        block_red4(su.p2.red4, s, lane, acc);
        if (s == 0)
            *(float4*)&g_T[(b * 9 + tp) * HID_ + lane * 4] = acc;
        __syncthreads();
    }
    grid_bar();

    // =====================================================================
    // Phase 3: 200 tasks (cls x b). Each task: recompute b's GN->smem (cheap),
    //          then conv2 GEMV with lanes on outputs, warps on i-chunks.
    // =====================================================================
    for (int t = blk; t < 200; t += grid) {
        int cls = t >> 3, b = t & 7;
        int orc = cls / 5, occ = cls % 5;

        if (tid < HID_) {
            int o = tid;
            float Tl[9];
            #pragma unroll
            for (int t9 = 0; t9 < 9; t9++) Tl[t9] = g_T[(b * 9 + t9) * HID_ + o];
            float btv = bt[o];

            float c9[9];
            for (int rc = 0; rc < 3; rc++)
                for (int cc = 0; cc < 3; cc++) {
                    float sum = btv;
                    for (int kh = 0; kh < 3; kh++) {
                        if ((rc == 0 && kh == 0) || (rc == 2 && kh == 2)) continue;
                        for (int kw = 0; kw < 3; kw++) {
                            if ((cc == 0 && kw == 0) || (cc == 2 && kw == 2)) continue;
                            sum += Tl[kh * 3 + kw];
                        }
                    }
                    c9[rc * 3 + cc] = sum;
                }

            const float rowcnt[3] = {1.f, (float)(H_ - 2), 1.f};
            const float colcnt[3] = {1.f, (float)(W_ - 2), 1.f};
            float area[9];
            for (int rc = 0; rc < 3; rc++)
                for (int cc = 0; cc < 3; cc++)
                    area[rc * 3 + cc] = rowcnt[rc] * colcnt[cc];

            const float inv = 1.0f / (16.0f * (float)HW_);
            float sm = 0.f;
            for (int k = 0; k < 9; k++) sm += area[k] * c9[k];
            for (int off = 8; off >= 1; off >>= 1) sm += __shfl_xor_sync(0xffffffffu, sm, off);
            float mean = sm * inv;

            float d = 0.f;
            for (int k = 0; k < 9; k++) { float tt = c9[k] - mean; d += area[k] * tt * tt; }
            for (int off = 8; off >= 1; off >>= 1) d += __shfl_xor_sync(0xffffffffu, d, off);
            float rstd = rsqrtf(d * inv + 1e-5f);

            float ga = g1[o], be = b1g[o];
            for (int k = 0; k < 9; k++)
                su.p3.g9b[k * HID_ + o] = gelu_((c9[k] - mean) * rstd * ga + be);
        }
        __syncthreads();

        float4 acc = make_float4(0.f, 0.f, 0.f, 0.f);
        for (int kh = 0; kh < 3; kh++) {
            int ir = c_map[orc][kh];
            if (ir < 0) continue;
            for (int kw = 0; kw < 3; kw++) {
                int ic = c_map[occ][kw];
                if (ic < 0) continue;
                float4 g4 = *(const float4*)&su.p3.g9b[(ir * 3 + ic) * HID_ + s * 4];
                const float* wb = Wc + ((size_t)(kh * 3 + kw) * HID_ + s * 4) * HID_ + lane * 4;
                #pragma unroll
                for (int k = 0; k < 4; k++) {
                    float gk = (&g4.x)[k];
                    float4 w = *(const float4*)(wb + (size_t)k * HID_);
                    acc.x = fmaf(gk, w.x, acc.x);
                    acc.y = fmaf(gk, w.y, acc.y);
                    acc.z = fmaf(gk, w.z, acc.z);
                    acc.w = fmaf(gk, w.w, acc.w);
                }
            }
        }
        block_red4(su.p3.red4, s, lane, acc);
        if (s == 0) {
            float4 bcv = *(const float4*)&bc[lane * 4];
            acc.x = gelu_(acc.x + bcv.x);
            acc.y = gelu_(acc.y + bcv.y);
            acc.z = gelu_(acc.z + bcv.z);
            acc.w = gelu_(acc.w + bcv.w);
            *(float4*)&g_F25[(b * 25 + cls) * HID_ + lane * 4] = acc;
        }
        __syncthreads();
    }
    grid_bar();

    // =====================================================================
    // Phase 4: 208 tasks (b x 26): cls<25 -> Y + s25 ; cls==25 -> base
    // =====================================================================
    for (int t = blk; t < 208; t += grid) {
        int b = t / 26, cls = t % 26;
        float4 x4;
        const float* wb;
        if (cls < 25) {
            x4 = *(const float4*)&g_F25[(b * 25 + cls) * HID_ + s * 4];
            wb = W1 + (size_t)(s * 4) * HID_ + lane * 4;
        } else {
            x4 = *(const float4*)&g_lc[b * HID_ + s * 4];
            wb = W1 + (size_t)(HID_ + s * 4) * HID_ + lane * 4;
        }
        float4 acc = make_float4(0.f, 0.f, 0.f, 0.f);
        #pragma unroll
        for (int k = 0; k < 4; k++) {
            float xk = (&x4.x)[k];
            float4 w = *(const float4*)(wb + (size_t)k * HID_);
            acc.x = fmaf(xk, w.x, acc.x);
            acc.y = fmaf(xk, w.y, acc.y);
            acc.z = fmaf(xk, w.z, acc.z);
            acc.w = fmaf(xk, w.w, acc.w);
        }
        block_red4(su.p4.red4, s, lane, acc);
        if (s == 0) {
            if (cls < 25) {
                *(float4*)&g_Y[(b * 25 + cls) * HID_ + lane * 4] = acc;
            } else {
                float4 b14 = *(const float4*)&b1[lane * 4];
                acc.x += b14.x; acc.y += b14.y; acc.z += b14.z; acc.w += b14.w;
                *(float4*)&g_base[b * HID_ + lane * 4] = acc;
            }
        }
        if (lane == 0)
            su.p4.sred[s] = x4.x * Wa[s * 4]     + x4.y * Wa[s * 4 + 1]
                          + x4.z * Wa[s * 4 + 2] + x4.w * Wa[s * 4 + 3];
        __syncthreads();
        if (tid < 32) {
            float sv = su.p4.sred[tid];
            for (int off = 16; off >= 1; off >>= 1)
                sv += __shfl_xor_sync(0xffffffffu, sv, off);
            if (tid == 0 && cls < 25) g_s25[b * 25 + cls] = sv + ba[0];
        }
        __syncthreads();
    }
    grid_bar();

    // =====================================================================
    // Phase 5: Pint (per block), interior fill, border attention -> packed out
    // =====================================================================
    {
        const int warp = s;
        if (warp < 8) {
            int b = warp;
            float4 y4  = *(const float4*)&g_Y[(b * 25 + 12) * HID_ + lane * 4];
            float4 bs4 = *(const float4*)&g_base[b * HID_ + lane * 4];
            float hx = gelu_(y4.x + bs4.x), hy = gelu_(y4.y + bs4.y);
            float hz = gelu_(y4.z + bs4.z), hw = gelu_(y4.w + bs4.w);
            float4 w2a = *(const float4*)&W2[lane * 8];
            float4 w2b = *(const float4*)&W2[lane * 8 + 4];
            float p0 = hx * w2a.x + hy * w2a.z + hz * w2b.x + hw * w2b.z;
            float p1 = hx * w2a.y + hy * w2a.w + hz * w2b.y + hw * w2b.w;
            for (int off = 16; off >= 1; off >>= 1) {
                p0 += __shfl_xor_sync(0xffffffffu, p0, off);
                p1 += __shfl_xor_sync(0xffffffffu, p1, off);
            }
            if (lane == 0) {
                su.p5.sPint[b][0] = p0 + b2[0];
                su.p5.sPint[b][1] = p1 + b2[1];
            }
        }
        __syncthreads();

        // interior masked slots -> Pint
        for (int idx = blk * 1024 + tid; idx < 8 * 4096; idx += grid * 1024) {
            int b = idx >> 12, pp = idx & 4095;
            if (pp < HW_) {
                int slot = g_slot[b * HW_ + pp];
                if (slot >= 0) {
                    int r = pp / W_, c = pp % W_;
                    if (r >= 4 && r <= H_ - 5 && c >= 4 && c <= W_ - 5) {
                        out[(b * HW_ + slot) * 2]     = su.p5.sPint[b][0];
                        out[(b * HW_ + slot) * 2 + 1] = su.p5.sPint[b][1];
                    }
                }
            }
        }

        // border attention (masked positions only)
        float* wcw = su.p5.wc[warp];
        const float b20 = b2[0], b21 = b2[1];
        const int nwarp = grid * 32;
        for (int task = blk * 32 + warp; task < NT4; task += nwarp) {
            int j = task >> 3, b = task & 7;
            int r, c;
            if (j < 176)      { r = j / 44;                 c = j % 44; }
            else if (j < 352) { int j2 = j - 176; r = 89 + j2 / 44; c = j2 % 44; }
            else              { int j3 = j - 352; r = 4 + j3 / 8;
                                int k = j3 % 8; c = (k < 4) ? k : 36 + k; }
            int p = r * W_ + c;
            int slot = g_slot[b * HW_ + p];
            if (slot < 0) continue;

            if (lane < 25) wcw[lane] = 0.f;
            __syncwarp();

            bool has = lane < MAXN_;
            float logit = -3.0e38f;
            int cls = 0;
            if (has) {
                int idx = nidx[p * MAXN_ + lane];
                int rr = idx / W_, c2 = idx % W_;
                int rc = (rr == 0) ? 0 : (rr == 1) ? 1 : (rr == H_ - 2) ? 3 : (rr == H_ - 1) ? 4 : 2;
                int cc = (c2 == 0) ? 0 : (c2 == 1) ? 1 : (c2 == W_ - 2) ? 3 : (c2 == W_ - 1) ? 4 : 2;
                cls = rc * 5 + cc;
                bool valid = (lane < ncnt[p]) && (mask[b * HW_ + idx] == 0);
                logit = valid ? g_s25[b * 25 + cls] : -10000.0f;
            }
            float m = logit;
            for (int off = 16; off >= 1; off >>= 1)
                m = fmaxf(m, __shfl_xor_sync(0xffffffffu, m, off));
            float e = has ? expf(logit - m) : 0.f;
            float se = e;
            for (int off = 16; off >= 1; off >>= 1)
                se += __shfl_xor_sync(0xffffffffu, se, off);
            float wgt = e / se;
            if (has && wgt != 0.f) atomicAdd(&wcw[cls], wgt);
            __syncwarp();

            float4 acc = *(const float4*)&g_base[b * HID_ + lane * 4];
            #pragma unroll
            for (int cl = 0; cl < 25; cl++) {
                float wv = wcw[cl];
                if (wv != 0.f) {
                    float4 y = *(const float4*)&g_Y[(b * 25 + cl) * HID_ + lane * 4];
                    acc.x = fmaf(wv, y.x, acc.x);
                    acc.y = fmaf(wv, y.y, acc.y);
                    acc.z = fmaf(wv, y.z, acc.z);
                    acc.w = fmaf(wv, y.w, acc.w);
                }
            }
            float hx = gelu_(acc.x), hy = gelu_(acc.y), hz = gelu_(acc.z), hw = gelu_(acc.w);
            float4 w2a = *(const float4*)&W2[lane * 8];
            float4 w2b = *(const float4*)&W2[lane * 8 + 4];
            float p0 = hx * w2a.x + hy * w2a.z + hz * w2b.x + hw * w2b.z;
            float p1 = hx * w2a.y + hy * w2a.w + hz * w2b.y + hw * w2b.w;
            for (int off = 16; off >= 1; off >>= 1) {
                p0 += __shfl_xor_sync(0xffffffffu, p0, off);
                p1 += __shfl_xor_sync(0xffffffffu, p1, off);
            }
            if (lane == 0) {
                out[(b * HW_ + slot) * 2]     = p0 + b20;
                out[(b * HW_ + slot) * 2 + 1] = p1 + b21;
            }
            __syncwarp();
        }
    }
}

// ---------------------------------------------------------------------------
// kernel_launch — single persistent node
// ---------------------------------------------------------------------------
extern "C" void kernel_launch(void* const* d_in, const int* in_sizes, int n_in,
                              void* d_out, int out_size) {
    const float* latent = (const float*)d_in[1];
    const int*   mask   = (const int*)  d_in[2];
    const int*   nidx   = (const int*)  d_in[3];
    const int*   ncnt   = (const int*)  d_in[4];
    const float* Wl = (const float*)d_in[5];
    const float* bl = (const float*)d_in[6];
    const float* Wt = (const float*)d_in[7];
    const float* bt = (const float*)d_in[8];
    const float* g1 = (const float*)d_in[9];
    const float* b1g= (const float*)d_in[10];
    const float* Wc = (const float*)d_in[11];
    const float* bc = (const float*)d_in[12];
    const float* Wa = (const float*)d_in[13];
    const float* ba = (const float*)d_in[14];
    const float* W1 = (const float*)d_in[15];
    const float* b1 = (const float*)d_in[16];
    const float* W2 = (const float*)d_in[17];
    const float* b2 = (const float*)d_in[18];

    int nsm = 148;
    cudaDeviceGetAttribute(&nsm, cudaDevAttrMultiProcessorCount, 0);

    kFused<<<nsm, 1024>>>(latent, mask, nidx, ncnt,
                          Wl, bl, Wt, bt, g1, b1g, Wc, bc,
                          Wa, ba, W1, b1, W2, b2,
                          (float*)d_out);
}

// round 9
// speedup vs baseline: 2.0095x; 1.1568x over previous
#include <cuda_runtime.h>
#include <math.h>

// ---------------------------------------------------------------------------
// Problem constants
// ---------------------------------------------------------------------------
constexpr int H_    = 93;
constexpr int W_    = 44;
constexpr int HW_   = H_ * W_;      // 4092
constexpr int B_    = 8;
constexpr int HID_  = 128;
constexpr int LAT_  = 1024;
constexpr int MAXN_ = 24;
constexpr int OFF1  = B_ * HW_ * 2; // 65472  (mask_indices start, as float)
constexpr int OFF2  = 2 * OFF1;     // 130944 (valid_mask start, as float)
constexpr int NT4   = 8256;         // border warp-tasks (1032 positions x 8 b)

// ---------------------------------------------------------------------------
// Scratch (__device__ globals: no allocation allowed)
// ---------------------------------------------------------------------------
__device__ __align__(16) float g_T   [B_ * 9 * HID_];   // taps
__device__ __align__(16) float g_s25 [B_ * 25];
__device__ __align__(16) float g_Y   [B_ * 25 * HID_];
__device__ __align__(16) float g_base[B_ * HID_];
__device__ int g_slot[B_ * HW_];                        // packed slot or -1
__device__ unsigned g_bar;                              // monotonic barrier

__device__ __forceinline__ float gelu_(float x) {
    return 0.5f * x * (1.0f + erff(x * 0.70710678118654752440f));
}

// rowmap[out_row_class][tap] -> input row-class (0=top,1=mid,2=bot), -1 = OOB
__constant__ int c_map[5][3] = {
    {-1, 0, 1}, { 0, 1, 1}, { 1, 1, 1}, { 1, 1, 2}, { 1, 2,-1},
};

// ---------------------------------------------------------------------------
// Software grid barrier (monotonic counter; grid == #SMs, occupancy 1)
// ---------------------------------------------------------------------------
__device__ __forceinline__ void grid_bar() {
    __syncthreads();
    if (threadIdx.x == 0) {
        __threadfence();
        unsigned old = atomicAdd(&g_bar, 1u);
        unsigned target = old - (old % gridDim.x) + gridDim.x;
        while (*(volatile unsigned*)&g_bar < target) { __nanosleep(32); }
        __threadfence();
    }
    __syncthreads();
}

// ---------------------------------------------------------------------------
// Block-wide reduction of per-warp float4 partials (32 warps -> warp 0).
// Lanes own 4 contiguous outputs; warp s holds the partial for i-chunk s.
// ---------------------------------------------------------------------------
__device__ __forceinline__ void block_red4(float4* red4, int s, int lane, float4& acc) {
    red4[s * 32 + lane] = acc;
    __syncthreads();
    #pragma unroll
    for (int st = 16; st >= 1; st >>= 1) {
        if (s < st) {
            float4 o = red4[(s + st) * 32 + lane];
            float4 m = red4[s * 32 + lane];
            m.x += o.x; m.y += o.y; m.z += o.z; m.w += o.w;
            red4[s * 32 + lane] = m;
        }
        __syncthreads();
    }
    if (s == 0) acc = red4[lane];
}

// ---------------------------------------------------------------------------
// Shared memory union (max member ~21.2 KB < 48 KB static limit)
// ---------------------------------------------------------------------------
union __align__(16) SmemU {
    struct { float4 red4[1024]; float s_lc[HID_]; int wsum[32]; } pa;
    struct { float4 red4[1024]; float g9b[9 * HID_]; float sF25[HID_]; float sred[32]; } pb;
    struct { float wc[32][25]; float sPint[8][2]; } pc;
};

// ---------------------------------------------------------------------------
// The one persistent kernel — 3 phases, 2 grid barriers
// ---------------------------------------------------------------------------
__global__ __launch_bounds__(1024, 1) void kFused(
    const float* __restrict__ lat,  const int* __restrict__ mask,
    const int* __restrict__ nidx,   const int* __restrict__ ncnt,
    const float* __restrict__ Wl,   const float* __restrict__ bl,
    const float* __restrict__ Wt,   const float* __restrict__ bt,
    const float* __restrict__ g1,   const float* __restrict__ b1g,
    const float* __restrict__ Wc,   const float* __restrict__ bc,
    const float* __restrict__ Wa,   const float* __restrict__ ba,
    const float* __restrict__ W1,   const float* __restrict__ b1,
    const float* __restrict__ W2,   const float* __restrict__ b2,
    float* __restrict__ out) {

    __shared__ SmemU su;
    const int tid  = threadIdx.x;
    const int blk  = blockIdx.x;
    const int grid = gridDim.x;
    const int lane = tid & 31;
    const int s    = tid >> 5;      // warp id = i-chunk for GEMV phases

    // =====================================================================
    // Phase A: 88 tasks, 1 wave.
    //   t <  72: (b, tap): recompute lc in-block, then tap GEMV -> g_T
    //   t <  80: (b): recompute lc, then base GEMV (W1[128:]) -> g_base
    //   t <  88: (b): mask scan + output init + g_slot
    // =====================================================================
    for (int t = blk; t < 88; t += grid) {
        if (t < 80) {
            int b, tp;
            if (t < 72) { b = t / 9; tp = t % 9; }
            else        { b = t - 72; tp = -1;   }

            // --- lc = gelu(lat[b] @ Wl + bl), warp s does i in [s*32,(s+1)*32)
            {
                const float* xb  = lat + b * LAT_ + s * 32;
                const float* wbl = Wl + (size_t)(s * 32) * HID_ + lane * 4;
                float4 acc = make_float4(0.f, 0.f, 0.f, 0.f);
                #pragma unroll 8
                for (int k = 0; k < 32; k++) {
                    float xk = xb[k];
                    float4 w = *(const float4*)(wbl + (size_t)k * HID_);
                    acc.x = fmaf(xk, w.x, acc.x);
                    acc.y = fmaf(xk, w.y, acc.y);
                    acc.z = fmaf(xk, w.z, acc.z);
                    acc.w = fmaf(xk, w.w, acc.w);
                }
                block_red4(su.pa.red4, s, lane, acc);
                if (s == 0) {
                    float4 blv = *(const float4*)&bl[lane * 4];
                    acc.x = gelu_(acc.x + blv.x);
                    acc.y = gelu_(acc.y + blv.y);
                    acc.z = gelu_(acc.z + blv.z);
                    acc.w = gelu_(acc.w + blv.w);
                    *(float4*)&su.pa.s_lc[lane * 4] = acc;
                }
                __syncthreads();
            }

            // --- second GEMV: tap (Wt[tp]) or base (W1[128:] + b1)
            float4 x4 = *(const float4*)&su.pa.s_lc[s * 4];
            const float* wb2 = (tp >= 0)
                ? Wt + (size_t)tp * HID_ * HID_ + (size_t)(s * 4) * HID_ + lane * 4
                : W1 + (size_t)(HID_ + s * 4) * HID_ + lane * 4;
            float4 acc2 = make_float4(0.f, 0.f, 0.f, 0.f);
            #pragma unroll
            for (int k = 0; k < 4; k++) {
                float xk = (&x4.x)[k];
                float4 w = *(const float4*)(wb2 + (size_t)k * HID_);
                acc2.x = fmaf(xk, w.x, acc2.x);
                acc2.y = fmaf(xk, w.y, acc2.y);
                acc2.z = fmaf(xk, w.z, acc2.z);
                acc2.w = fmaf(xk, w.w, acc2.w);
            }
            block_red4(su.pa.red4, s, lane, acc2);
            if (s == 0) {
                if (tp >= 0) {
                    *(float4*)&g_T[(b * 9 + tp) * HID_ + lane * 4] = acc2;
                } else {
                    float4 b14 = *(const float4*)&b1[lane * 4];
                    acc2.x += b14.x; acc2.y += b14.y; acc2.z += b14.z; acc2.w += b14.w;
                    *(float4*)&g_base[b * HID_ + lane * 4] = acc2;
                }
            }
            __syncthreads();
        } else {
            // --- scan task for batch b
            int b = t - 80;
            int warp = s;
            int base = tid * 4;
            int m[4], loc[4];
            int sc = 0;
            for (int j = 0; j < 4; j++) {
                int p = base + j;
                int mm = (p < HW_) ? (mask[b * HW_ + p] > 0) : 0;
                m[j] = mm; loc[j] = sc; sc += mm;
            }
            int v = sc;
            for (int off = 1; off < 32; off <<= 1) {
                int u = __shfl_up_sync(0xffffffffu, v, off);
                if (lane >= off) v += u;
            }
            if (lane == 31) su.pa.wsum[warp] = v;
            __syncthreads();
            if (warp == 0) {
                int wv = su.pa.wsum[lane];
                for (int off = 1; off < 32; off <<= 1) {
                    int u = __shfl_up_sync(0xffffffffu, wv, off);
                    if (lane >= off) wv += u;
                }
                su.pa.wsum[lane] = wv;
            }
            __syncthreads();
            int excl = (v - sc) + (warp > 0 ? su.pa.wsum[warp - 1] : 0);
            int nm = su.pa.wsum[31];

            for (int j = 0; j < 4; j++) {
                int p = base + j;
                if (p < HW_) {
                    if (m[j]) {
                        int slot = excl + loc[j];
                        out[OFF1 + (b * HW_ + slot) * 2]     = (float)(p / W_);
                        out[OFF1 + (b * HW_ + slot) * 2 + 1] = (float)(p % W_);
                        g_slot[b * HW_ + p] = slot;
                    } else {
                        g_slot[b * HW_ + p] = -1;
                    }
                }
            }
            for (int sl = nm + tid; sl < HW_; sl += 1024) {
                out[(b * HW_ + sl) * 2]            = 0.f;
                out[(b * HW_ + sl) * 2 + 1]        = 0.f;
                out[OFF1 + (b * HW_ + sl) * 2]     = 0.f;
                out[OFF1 + (b * HW_ + sl) * 2 + 1] = 0.f;
            }
            for (int sl = tid; sl < HW_; sl += 1024)
                out[OFF2 + b * HW_ + sl] = (sl < nm) ? 1.f : 0.f;
        }
    }
    grid_bar();

    // =====================================================================
    // Phase B: 200 tasks (cls x b): GN recompute -> conv2 -> F25 (smem)
    //          -> Y GEMV + s25. No F25 global round-trip.
    // =====================================================================
    for (int t = blk; t < 200; t += grid) {
        int cls = t >> 3, b = t & 7;
        int orc = cls / 5, occ = cls % 5;

        // --- per-batch GN into smem (128 threads)
        if (tid < HID_) {
            int o = tid;
            float Tl[9];
            #pragma unroll
            for (int t9 = 0; t9 < 9; t9++) Tl[t9] = g_T[(b * 9 + t9) * HID_ + o];
            float btv = bt[o];

            float c9[9];
            for (int rc = 0; rc < 3; rc++)
                for (int cc = 0; cc < 3; cc++) {
                    float sum = btv;
                    for (int kh = 0; kh < 3; kh++) {
                        if ((rc == 0 && kh == 0) || (rc == 2 && kh == 2)) continue;
                        for (int kw = 0; kw < 3; kw++) {
                            if ((cc == 0 && kw == 0) || (cc == 2 && kw == 2)) continue;
                            sum += Tl[kh * 3 + kw];
                        }
                    }
                    c9[rc * 3 + cc] = sum;
                }

            const float rowcnt[3] = {1.f, (float)(H_ - 2), 1.f};
            const float colcnt[3] = {1.f, (float)(W_ - 2), 1.f};
            float area[9];
            for (int rc = 0; rc < 3; rc++)
                for (int cc = 0; cc < 3; cc++)
                    area[rc * 3 + cc] = rowcnt[rc] * colcnt[cc];

            const float inv = 1.0f / (16.0f * (float)HW_);
            float sm = 0.f;
            for (int k = 0; k < 9; k++) sm += area[k] * c9[k];
            for (int off = 8; off >= 1; off >>= 1) sm += __shfl_xor_sync(0xffffffffu, sm, off);
            float mean = sm * inv;

            float d = 0.f;
            for (int k = 0; k < 9; k++) { float tt = c9[k] - mean; d += area[k] * tt * tt; }
            for (int off = 8; off >= 1; off >>= 1) d += __shfl_xor_sync(0xffffffffu, d, off);
            float rstd = rsqrtf(d * inv + 1e-5f);

            float ga = g1[o], be = b1g[o];
            for (int k = 0; k < 9; k++)
                su.pb.g9b[k * HID_ + o] = gelu_((c9[k] - mean) * rstd * ga + be);
        }
        __syncthreads();

        // --- conv2 GEMV
        float4 acc = make_float4(0.f, 0.f, 0.f, 0.f);
        for (int kh = 0; kh < 3; kh++) {
            int ir = c_map[orc][kh];
            if (ir < 0) continue;
            for (int kw = 0; kw < 3; kw++) {
                int ic = c_map[occ][kw];
                if (ic < 0) continue;
                float4 g4 = *(const float4*)&su.pb.g9b[(ir * 3 + ic) * HID_ + s * 4];
                const float* wb = Wc + ((size_t)(kh * 3 + kw) * HID_ + s * 4) * HID_ + lane * 4;
                #pragma unroll
                for (int k = 0; k < 4; k++) {
                    float gk = (&g4.x)[k];
                    float4 w = *(const float4*)(wb + (size_t)k * HID_);
                    acc.x = fmaf(gk, w.x, acc.x);
                    acc.y = fmaf(gk, w.y, acc.y);
                    acc.z = fmaf(gk, w.z, acc.z);
                    acc.w = fmaf(gk, w.w, acc.w);
                }
            }
        }
        block_red4(su.pb.red4, s, lane, acc);
        if (s == 0) {
            float4 bcv = *(const float4*)&bc[lane * 4];
            acc.x = gelu_(acc.x + bcv.x);
            acc.y = gelu_(acc.y + bcv.y);
            acc.z = gelu_(acc.z + bcv.z);
            acc.w = gelu_(acc.w + bcv.w);
            *(float4*)&su.pb.sF25[lane * 4] = acc;
        }
        __syncthreads();

        // --- Y = F25 @ W1[:128]  and  s25 = F25 . Wa + ba
        float4 x4 = *(const float4*)&su.pb.sF25[s * 4];
        const float* wb1 = W1 + (size_t)(s * 4) * HID_ + lane * 4;
        float4 acc2 = make_float4(0.f, 0.f, 0.f, 0.f);
        #pragma unroll
        for (int k = 0; k < 4; k++) {
            float xk = (&x4.x)[k];
            float4 w = *(const float4*)(wb1 + (size_t)k * HID_);
            acc2.x = fmaf(xk, w.x, acc2.x);
            acc2.y = fmaf(xk, w.y, acc2.y);
            acc2.z = fmaf(xk, w.z, acc2.z);
            acc2.w = fmaf(xk, w.w, acc2.w);
        }
        block_red4(su.pb.red4, s, lane, acc2);
        if (s == 0)
            *(float4*)&g_Y[(b * 25 + cls) * HID_ + lane * 4] = acc2;
        if (lane == 0)
            su.pb.sred[s] = x4.x * Wa[s * 4]     + x4.y * Wa[s * 4 + 1]
                          + x4.z * Wa[s * 4 + 2] + x4.w * Wa[s * 4 + 3];
        __syncthreads();
        if (tid < 32) {
            float sv = su.pb.sred[tid];
            for (int off = 16; off >= 1; off >>= 1)
                sv += __shfl_xor_sync(0xffffffffu, sv, off);
            if (tid == 0) g_s25[b * 25 + cls] = sv + ba[0];
        }
        __syncthreads();
    }
    grid_bar();

    // =====================================================================
    // Phase C: Pint (per block), interior fill, border attention -> packed out
    // =====================================================================
    {
        const int warp = s;
        if (warp < 8) {
            int b = warp;
            float4 y4  = *(const float4*)&g_Y[(b * 25 + 12) * HID_ + lane * 4];
            float4 bs4 = *(const float4*)&g_base[b * HID_ + lane * 4];
            float hx = gelu_(y4.x + bs4.x), hy = gelu_(y4.y + bs4.y);
            float hz = gelu_(y4.z + bs4.z), hw = gelu_(y4.w + bs4.w);
            float4 w2a = *(const float4*)&W2[lane * 8];
            float4 w2b = *(const float4*)&W2[lane * 8 + 4];
            float p0 = hx * w2a.x + hy * w2a.z + hz * w2b.x + hw * w2b.z;
            float p1 = hx * w2a.y + hy * w2a.w + hz * w2b.y + hw * w2b.w;
            for (int off = 16; off >= 1; off >>= 1) {
                p0 += __shfl_xor_sync(0xffffffffu, p0, off);
                p1 += __shfl_xor_sync(0xffffffffu, p1, off);
            }
            if (lane == 0) {
                su.pc.sPint[b][0] = p0 + b2[0];
                su.pc.sPint[b][1] = p1 + b2[1];
            }
        }
        __syncthreads();

        // interior masked slots -> Pint
        for (int idx = blk * 1024 + tid; idx < 8 * 4096; idx += grid * 1024) {
            int b = idx >> 12, pp = idx & 4095;
            if (pp < HW_) {
                int slot = g_slot[b * HW_ + pp];
                if (slot >= 0) {
                    int r = pp / W_, c = pp % W_;
                    if (r >= 4 && r <= H_ - 5 && c >= 4 && c <= W_ - 5) {
                        out[(b * HW_ + slot) * 2]     = su.pc.sPint[b][0];
                        out[(b * HW_ + slot) * 2 + 1] = su.pc.sPint[b][1];
                    }
                }
            }
        }

        // border attention (masked positions only)
        float* wcw = su.pc.wc[warp];
        const float b20 = b2[0], b21 = b2[1];
        const int nwarp = grid * 32;
        for (int task = blk * 32 + warp; task < NT4; task += nwarp) {
            int j = task >> 3, b = task & 7;
            int r, c;
            if (j < 176)      { r = j / 44;                 c = j % 44; }
            else if (j < 352) { int j2 = j - 176; r = 89 + j2 / 44; c = j2 % 44; }
            else              { int j3 = j - 352; r = 4 + j3 / 8;
                                int k = j3 % 8; c = (k < 4) ? k : 36 + k; }
            int p = r * W_ + c;
            int slot = g_slot[b * HW_ + p];
            if (slot < 0) continue;

            if (lane < 25) wcw[lane] = 0.f;
            __syncwarp();

            bool has = lane < MAXN_;
            float logit = -3.0e38f;
            int cls = 0;
            if (has) {
                int idx = nidx[p * MAXN_ + lane];
                int rr = idx / W_, c2 = idx % W_;
                int rc = (rr == 0) ? 0 : (rr == 1) ? 1 : (rr == H_ - 2) ? 3 : (rr == H_ - 1) ? 4 : 2;
                int cc = (c2 == 0) ? 0 : (c2 == 1) ? 1 : (c2 == W_ - 2) ? 3 : (c2 == W_ - 1) ? 4 : 2;
                cls = rc * 5 + cc;
                bool valid = (lane < ncnt[p]) && (mask[b * HW_ + idx] == 0);
                logit = valid ? g_s25[b * 25 + cls] : -10000.0f;
            }
            float m = logit;
            for (int off = 16; off >= 1; off >>= 1)
                m = fmaxf(m, __shfl_xor_sync(0xffffffffu, m, off));
            float e = has ? expf(logit - m) : 0.f;
            float se = e;
            for (int off = 16; off >= 1; off >>= 1)
                se += __shfl_xor_sync(0xffffffffu, se, off);
            float wgt = e / se;
            if (has && wgt != 0.f) atomicAdd(&wcw[cls], wgt);
            __syncwarp();

            float4 acc = *(const float4*)&g_base[b * HID_ + lane * 4];
            #pragma unroll
            for (int cl = 0; cl < 25; cl++) {
                float wv = wcw[cl];
                if (wv != 0.f) {
                    float4 y = *(const float4*)&g_Y[(b * 25 + cl) * HID_ + lane * 4];
                    acc.x = fmaf(wv, y.x, acc.x);
                    acc.y = fmaf(wv, y.y, acc.y);
                    acc.z = fmaf(wv, y.z, acc.z);
                    acc.w = fmaf(wv, y.w, acc.w);
                }
            }
            float hx = gelu_(acc.x), hy = gelu_(acc.y), hz = gelu_(acc.z), hw = gelu_(acc.w);
            float4 w2a = *(const float4*)&W2[lane * 8];
            float4 w2b = *(const float4*)&W2[lane * 8 + 4];
            float p0 = hx * w2a.x + hy * w2a.z + hz * w2b.x + hw * w2b.z;
            float p1 = hx * w2a.y + hy * w2a.w + hz * w2b.y + hw * w2b.w;
            for (int off = 16; off >= 1; off >>= 1) {
                p0 += __shfl_xor_sync(0xffffffffu, p0, off);
                p1 += __shfl_xor_sync(0xffffffffu, p1, off);
            }
            if (lane == 0) {
                out[(b * HW_ + slot) * 2]     = p0 + b20;
                out[(b * HW_ + slot) * 2 + 1] = p1 + b21;
            }
            __syncwarp();
        }
    }
}

// ---------------------------------------------------------------------------
// kernel_launch — single persistent node
// ---------------------------------------------------------------------------
extern "C" void kernel_launch(void* const* d_in, const int* in_sizes, int n_in,
                              void* d_out, int out_size) {
    const float* latent = (const float*)d_in[1];
    const int*   mask   = (const int*)  d_in[2];
    const int*   nidx   = (const int*)  d_in[3];
    const int*   ncnt   = (const int*)  d_in[4];
    const float* Wl = (const float*)d_in[5];
    const float* bl = (const float*)d_in[6];
    const float* Wt = (const float*)d_in[7];
    const float* bt = (const float*)d_in[8];
    const float* g1 = (const float*)d_in[9];
    const float* b1g= (const float*)d_in[10];
    const float* Wc = (const float*)d_in[11];
    const float* bc = (const float*)d_in[12];
    const float* Wa = (const float*)d_in[13];
    const float* ba = (const float*)d_in[14];
    const float* W1 = (const float*)d_in[15];
    const float* b1 = (const float*)d_in[16];
    const float* W2 = (const float*)d_in[17];
    const float* b2 = (const float*)d_in[18];

    int nsm = 148;
    cudaDeviceGetAttribute(&nsm, cudaDevAttrMultiProcessorCount, 0);

    kFused<<<nsm, 1024>>>(latent, mask, nidx, ncnt,
                          Wl, bl, Wt, bt, g1, b1g, Wc, bc,
                          Wa, ba, W1, b1, W2, b2,
                          (float*)d_out);
}